// round 10
// baseline (speedup 1.0000x reference)
#include <cuda_runtime.h>
#include <math.h>

#define RBM_B 2048
#define RBM_V 4096
#define RBM_H 1024

// Scratch (device globals: allocation-free rule)
static __device__ float g_WT[(size_t)RBM_H * RBM_V];   // 16 MB  W transposed [H,V]
static __device__ float g_h [(size_t)RBM_B * RBM_H];   //  8 MB  current h
static __device__ float g_v [(size_t)RBM_B * RBM_V];   // 32 MB  current v
static __device__ float g_pos[RBM_B * 16];             // pos partials (16 n-tiles, BN=64)
static __device__ float g_neg[RBM_B * 64];             // neg partials (64 n-tiles, BN=64)

typedef unsigned long long u64;

// packed f32x2 FMA (full-rate fp32 on sm_103a; per-lane rounding == scalar FFMA)
__device__ __forceinline__ void ffma2(u64& d, u64 a, u64 b) {
    asm("fma.rn.f32x2 %0, %1, %2, %0;" : "+l"(d) : "l"(a), "l"(b));
}
__device__ __forceinline__ u64 dup32(float v) {
    unsigned u = __float_as_uint(v);
    return (u64)u | ((u64)u << 32);
}
__device__ __forceinline__ void cp16(unsigned smem, const void* g) {
    asm volatile("cp.async.ca.shared.global [%0], [%1], 16;" :: "r"(smem), "l"(g));
}
__device__ __forceinline__ void cp_commit() { asm volatile("cp.async.commit_group;"); }
__device__ __forceinline__ void cp_wait0()  { asm volatile("cp.async.wait_group 0;"); }

// ---------------- transpose W[V,H] -> WT[H,V] ----------------
__global__ void k_transpose(const float* __restrict__ W, float* __restrict__ WT) {
    __shared__ float t[32][33];
    int h0 = blockIdx.x * 32, v0 = blockIdx.y * 32;
#pragma unroll
    for (int i = 0; i < 4; ++i)
        t[threadIdx.y + 8*i][threadIdx.x] =
            W[(size_t)(v0 + threadIdx.y + 8*i) * RBM_H + h0 + threadIdx.x];
    __syncthreads();
#pragma unroll
    for (int i = 0; i < 4; ++i)
        WT[(size_t)(h0 + threadIdx.y + 8*i) * RBM_V + v0 + threadIdx.x] =
            t[threadIdx.x][threadIdx.y + 8*i];
}

// ---------------- fused GEMM + bias + sigmoid-Bernoulli sample (+score) ----------------
// C[M,N] = A[M,K] * Bm[K,N]; A binary {0,1}.
// CRITICAL: one accumulator per output element, strict ascending-k fma.rn chain
// (bit-identical logits to all passing rounds). SIMD pairs along n.
// BM=128, BN=64, BK=16, 128 threads, thread tile 8m x 8n.
// As permuted layout: u64 index j = q*32 + ty*2 + h  <->  row m = ty*8 + q*2 + h,
// so each warp's A-read (ulonglong2 at j = q*32+ty*2) is 64B-contiguous: 1 wavefront.
// B tiles fetched with cp.async (plain copy, overlapped with compute).
template<int SCORE>
__global__ __launch_bounds__(128, 3)
void k_gemm_sample(const float* __restrict__ A, const float* __restrict__ Bm,
                   const float* __restrict__ bias, const float* __restrict__ U,
                   float* __restrict__ Out, float* __restrict__ Score,
                   int K, int N)
{
    constexpr int BM = 128, BN = 64, BK = 16;
    __shared__ __align__(16) u64   As[2][BK][BM];      // dup-A, permuted: 32 KB
    __shared__ __align__(16) float Bs[2][BK][BN];      // plain B: 8 KB

    const int tid = threadIdx.x;
    const int tx = tid & 7, ty = tid >> 3;
    const int m0 = blockIdx.y * BM, n0 = blockIdx.x * BN;

    // A loader: thread u = tid stores to As[c][u]; the row it must load is
    // m(u) = (u>>1 & 15)*8 + (u>>5)*2 + (u&1)  (inverse of j = q*32+ty*2+h).
    const int arow = ((tid >> 1) & 15) * 8 + (tid >> 5) * 2 + (tid & 1);
    const float* Aload = A + (size_t)(m0 + arow) * K;

    // B via cp.async: 256 16B-chunks per tile, 2 per thread.
    const unsigned bs_base = (unsigned)__cvta_generic_to_shared(&Bs[0][0][0]);
    const int bkk0 = (tid * 2) >> 4,     bco0 = ((tid * 2) & 15) * 4;
    const int bkk1 = (tid * 2 + 1) >> 4, bco1 = ((tid * 2 + 1) & 15) * 4;

    // acc[m 0..7][j 0..3]: u64 = fp32 pair, columns ((j>>1)*32 + tx*4 + 2*(j&1), +1)
    u64 acc[8][4];
#pragma unroll
    for (int m = 0; m < 8; ++m)
#pragma unroll
        for (int j = 0; j < 4; ++j) acc[m][j] = 0ull;

    float4 pa[4];

    // ---- prologue: tile 0 ----
    cp16(bs_base + (bkk0 * BN + bco0) * 4, Bm + (size_t)bkk0 * N + n0 + bco0);
    cp16(bs_base + (bkk1 * BN + bco1) * 4, Bm + (size_t)bkk1 * N + n0 + bco1);
    cp_commit();
#pragma unroll
    for (int q = 0; q < 4; ++q) pa[q] = *(const float4*)(Aload + q * 4);
#pragma unroll
    for (int c = 0; c < 16; ++c)
        As[0][c][tid] = dup32(((const float*)&pa[0])[c]);
    cp_wait0();
    __syncthreads();

    const int nk = K / BK;
    int buf = 0;
    for (int t = 0; t < nk; ++t) {
        if (t + 1 < nk) {
            const unsigned sb = bs_base + (buf ^ 1) * (BK * BN * 4);
            const float* Bg = Bm + (size_t)(t + 1) * BK * N + n0;
            cp16(sb + (bkk0 * BN + bco0) * 4, Bg + (size_t)bkk0 * N + bco0);
            cp16(sb + (bkk1 * BN + bco1) * 4, Bg + (size_t)bkk1 * N + bco1);
            cp_commit();
            const float* Ap = Aload + (t + 1) * BK;
#pragma unroll
            for (int q = 0; q < 4; ++q) pa[q] = *(const float4*)(Ap + q * 4);
        }
        // strict ascending-k serial accumulation (32 independent FFMA2 chains)
#pragma unroll
        for (int kk = 0; kk < BK; ++kk) {
            u64 ap[8];
#pragma unroll
            for (int q = 0; q < 4; ++q) {
                // rows (ty*8 + 2q, ty*8 + 2q + 1) at permuted index q*32 + ty*2
                ulonglong2 a2 = *(const ulonglong2*)&As[buf][kk][q * 32 + ty * 2];
                ap[q * 2] = a2.x; ap[q * 2 + 1] = a2.y;
            }
            u64 bp[4];
#pragma unroll
            for (int q = 0; q < 2; ++q) {
                ulonglong2 b2 = *(const ulonglong2*)&Bs[buf][kk][q * 32 + tx * 4];
                bp[q * 2] = b2.x; bp[q * 2 + 1] = b2.y;
            }
#pragma unroll
            for (int m = 0; m < 8; ++m)
#pragma unroll
                for (int j = 0; j < 4; ++j)
                    ffma2(acc[m][j], ap[m], bp[j]);
        }
        if (t + 1 < nk) {
            int nb = buf ^ 1;
#pragma unroll
            for (int c = 0; c < 16; ++c)
                As[nb][c][tid] = dup32(((const float*)&pa[0])[c]);
            cp_wait0();
        }
        __syncthreads();
        buf ^= 1;
    }

    // ---- epilogue: bias + sigmoid + Bernoulli + optional per-row score partial ----
    float biasv[8];
#pragma unroll
    for (int q = 0; q < 2; ++q)
        *(float4*)&biasv[q * 4] = *(const float4*)(bias + n0 + q * 32 + tx * 4);
#pragma unroll
    for (int m = 0; m < 8; ++m) {
        int gm = m0 + ty * 8 + m;
        float sp = 0.f;
#pragma unroll
        for (int q = 0; q < 2; ++q) {
            int gn = n0 + q * 32 + tx * 4;
            float4 u4 = *(const float4*)(U + (size_t)gm * N + gn);
            float2 e0 = *(float2*)&acc[m][q * 2];
            float2 e1 = *(float2*)&acc[m][q * 2 + 1];
            float l[4] = { e0.x + biasv[q*4],   e0.y + biasv[q*4+1],
                           e1.x + biasv[q*4+2], e1.y + biasv[q*4+3] };
            float s[4];
#pragma unroll
            for (int j = 0; j < 4; ++j) {
                float pr = 1.0f / (1.0f + expf(-l[j]));   // libdevice expf + IEEE div
                s[j] = (pr > ((const float*)&u4)[j]) ? 1.0f : 0.0f;
            }
            *(float4*)(Out + (size_t)gm * N + gn) = make_float4(s[0], s[1], s[2], s[3]);
            if (SCORE) sp += s[0]*l[0] + s[1]*l[1] + s[2]*l[2] + s[3]*l[3];
        }
        if (SCORE) {
            sp += __shfl_xor_sync(0xffffffffu, sp, 1);
            sp += __shfl_xor_sync(0xffffffffu, sp, 2);
            sp += __shfl_xor_sync(0xffffffffu, sp, 4);
            if (tx == 0) Score[(size_t)gm * gridDim.x + blockIdx.x] = sp;
        }
    }
}

// ---------------- finalize: out[b] = (v.b_v + pos) - (neg + h2.b_h) ----------------
__global__ void k_finalize(const float* __restrict__ visible, const float* __restrict__ b_v,
                           const float* __restrict__ b_h, float* __restrict__ out)
{
    int b = blockIdx.x, tid = threadIdx.x;
    float acc = 0.f;
    const float* vr = visible + (size_t)b * RBM_V;
    for (int i = tid; i < RBM_V; i += 256) acc += vr[i] * b_v[i];
    const float* hr = g_h + (size_t)b * RBM_H;            // g_h holds h2 here
    for (int i = tid; i < RBM_H; i += 256) acc -= hr[i] * b_h[i];
    if (tid < 16) acc += g_pos[b * 16 + tid];             // 16 n-tiles (BN=64, N=1024)
    if (tid < 64) acc -= g_neg[b * 64 + tid];             // 64 n-tiles (BN=64, N=4096)
    __shared__ float red[256];
    red[tid] = acc;
    __syncthreads();
    for (int o = 128; o; o >>= 1) { if (tid < o) red[tid] += red[tid + o]; __syncthreads(); }
    if (tid == 0) out[b] = red[0];
}

// ---------------- launch ----------------
extern "C" void kernel_launch(void* const* d_in, const int* in_sizes, int n_in,
                              void* d_out, int out_size)
{
    const float* visible = (const float*)d_in[0];
    const float* b_v     = (const float*)d_in[1];
    const float* b_h     = (const float*)d_in[2];
    const float* W       = (const float*)d_in[3];
    const float* u_h0    = (const float*)d_in[4];
    const float* u_v     = (const float*)d_in[5];
    const float* u_h     = (const float*)d_in[6];
    float* out = (float*)d_out;

    float *WT, *hb, *vb, *pos, *neg;
    cudaGetSymbolAddress((void**)&WT,  g_WT);
    cudaGetSymbolAddress((void**)&hb,  g_h);
    cudaGetSymbolAddress((void**)&vb,  g_v);
    cudaGetSymbolAddress((void**)&pos, g_pos);
    cudaGetSymbolAddress((void**)&neg, g_neg);

    k_transpose<<<dim3(RBM_H / 32, RBM_V / 32), dim3(32, 8)>>>(W, WT);

    dim3 blk(128);
    dim3 gH(RBM_H / 64, RBM_B / 128);   // (16, 16) = 256 CTAs
    dim3 gV(RBM_V / 64, RBM_B / 128);   // (64, 16) = 1024 CTAs

    const size_t BV = (size_t)RBM_B * RBM_V;
    const size_t BH = (size_t)RBM_B * RBM_H;

    // positive phase: h0 | data, fused pos-score
    k_gemm_sample<1><<<gH, blk>>>(visible, W,  b_h, u_h0,        hb, pos,    RBM_V, RBM_H);
    // Gibbs chain: v,h,v,h,v
    k_gemm_sample<0><<<gV, blk>>>(hb,      WT, b_v, u_v + 0*BV,  vb, nullptr, RBM_H, RBM_V);
    k_gemm_sample<0><<<gH, blk>>>(vb,      W,  b_h, u_h + 0*BH,  hb, nullptr, RBM_V, RBM_H);
    k_gemm_sample<0><<<gV, blk>>>(hb,      WT, b_v, u_v + 1*BV,  vb, nullptr, RBM_H, RBM_V);
    k_gemm_sample<0><<<gH, blk>>>(vb,      W,  b_h, u_h + 1*BH,  hb, nullptr, RBM_V, RBM_H);
    // last v-step: fused neg-score
    k_gemm_sample<2><<<gV, blk>>>(hb,      WT, b_v, u_v + 2*BV,  vb, neg,     RBM_H, RBM_V);

    k_finalize<<<RBM_B, 256>>>(visible, b_v, b_h, out);
}

// round 11
// speedup vs baseline: 1.0925x; 1.0925x over previous
#include <cuda_runtime.h>
#include <math.h>

#define RBM_B 2048
#define RBM_V 4096
#define RBM_H 1024

// Scratch (device globals: allocation-free rule)
static __device__ float g_WT[(size_t)RBM_H * RBM_V];   // 16 MB  W transposed [H,V]
static __device__ float g_h [(size_t)RBM_B * RBM_H];   //  8 MB  current h
static __device__ float g_v [(size_t)RBM_B * RBM_V];   // 32 MB  current v
static __device__ float g_pos[RBM_B * 16];             // pos partials (16 n-tiles, BN=64)
static __device__ float g_neg[RBM_B * 64];             // neg partials (64 n-tiles, BN=64)

typedef unsigned long long u64;

// packed f32x2 FMA (full-rate fp32 on sm_103a; per-lane rounding == scalar FFMA)
__device__ __forceinline__ void ffma2(u64& d, u64 a, u64 b) {
    asm("fma.rn.f32x2 %0, %1, %2, %0;" : "+l"(d) : "l"(a), "l"(b));
}
__device__ __forceinline__ u64 dup32(float v) {
    unsigned u = __float_as_uint(v);
    return (u64)u | ((u64)u << 32);
}

// ---------------- transpose W[V,H] -> WT[H,V] ----------------
__global__ void k_transpose(const float* __restrict__ W, float* __restrict__ WT) {
    __shared__ float t[32][33];
    int h0 = blockIdx.x * 32, v0 = blockIdx.y * 32;
#pragma unroll
    for (int i = 0; i < 4; ++i)
        t[threadIdx.y + 8*i][threadIdx.x] =
            W[(size_t)(v0 + threadIdx.y + 8*i) * RBM_H + h0 + threadIdx.x];
    __syncthreads();
#pragma unroll
    for (int i = 0; i < 4; ++i)
        WT[(size_t)(h0 + threadIdx.y + 8*i) * RBM_V + v0 + threadIdx.x] =
            t[threadIdx.x][threadIdx.y + 8*i];
}

// ---------------- fused GEMM + bias + sigmoid-Bernoulli sample (+score) ----------------
// C[M,N] = A[M,K] * Bm[K,N]; A binary {0,1}.
// CRITICAL: one accumulator per output element, strict ascending-k fma.rn chain
// (bit-identical logits to all passing rounds). SIMD pairs along n.
// BM=128, BN=64, BK=16, 128 threads, thread tile 8m x 8n.
// Permuted As: u64 index j = q*32 + ty*2 + h <-> row m = ty*8 + q*2 + h, so each
// warp's A-read (ulonglong2 at q*32 + ty*2) is 64B-contiguous: 1 wavefront.
// PIPE=1 (H-out, grid 256, <=2 CTA/SM): 2-deep register software pipeline over kk,
//   __launch_bounds__(128,2) for the extra registers (residency unaffected).
// PIPE=0 (V-out, grid 1024, 3 CTA/SM resident): plain body, bounds(128,3).
template<int SCORE, int PIPE>
__global__ __launch_bounds__(128, (PIPE ? 2 : 3))
void k_gemm_sample(const float* __restrict__ A, const float* __restrict__ Bm,
                   const float* __restrict__ bias, const float* __restrict__ U,
                   float* __restrict__ Out, float* __restrict__ Score,
                   int K, int N)
{
    constexpr int BM = 128, BN = 64, BK = 16;
    __shared__ __align__(16) u64   As[2][BK][BM];      // dup-A, permuted: 32 KB
    __shared__ __align__(16) float Bs[2][BK][BN];      // plain B: 8 KB

    const int tid = threadIdx.x;
    const int tx = tid & 7, ty = tid >> 3;
    const int m0 = blockIdx.y * BM, n0 = blockIdx.x * BN;

    // A loader: thread stores column tid; the row it loads is the permute-inverse.
    const int arow = ((tid >> 1) & 15) * 8 + (tid >> 5) * 2 + (tid & 1);
    const float* Aload = A + (size_t)(m0 + arow) * K;
    // B loader: 16 rows x 64 floats, 8 per thread.
    const int brow = tid >> 3, bcol = (tid & 7) * 8;
    const float* Bload = Bm + (size_t)brow * N + n0 + bcol;

    // acc[m 0..7][j 0..3]: u64 = fp32 pair, columns ((j>>1)*32 + tx*4 + 2*(j&1), +1)
    u64 acc[8][4];
#pragma unroll
    for (int m = 0; m < 8; ++m)
#pragma unroll
        for (int j = 0; j < 4; ++j) acc[m][j] = 0ull;

    float4 pa[4], pb[2];

    // ---- prologue: tile 0 ----
#pragma unroll
    for (int q = 0; q < 4; ++q) pa[q] = *(const float4*)(Aload + q * 4);
#pragma unroll
    for (int q = 0; q < 2; ++q) pb[q] = *(const float4*)(Bload + q * 4);
#pragma unroll
    for (int c = 0; c < 16; ++c)
        As[0][c][tid] = dup32(((const float*)&pa[0])[c]);
#pragma unroll
    for (int q = 0; q < 2; ++q)
        *(float4*)&Bs[0][brow][bcol + q * 4] = pb[q];
    __syncthreads();

    const int nk = K / BK;
    int buf = 0;
    for (int t = 0; t < nk; ++t) {
        if (t + 1 < nk) {
            const float* Ap = Aload + (t + 1) * BK;
            const float* Bp = Bload + (size_t)(t + 1) * BK * N;
#pragma unroll
            for (int q = 0; q < 4; ++q) pa[q] = *(const float4*)(Ap + q * 4);
#pragma unroll
            for (int q = 0; q < 2; ++q) pb[q] = *(const float4*)(Bp + q * 4);
        }
        // strict ascending-k serial accumulation (32 independent FFMA2 chains)
        if (PIPE) {
            u64 apr[2][8], bpr[2][4];
#pragma unroll
            for (int q = 0; q < 4; ++q) {
                ulonglong2 a2 = *(const ulonglong2*)&As[buf][0][q * 32 + ty * 2];
                apr[0][q * 2] = a2.x; apr[0][q * 2 + 1] = a2.y;
            }
#pragma unroll
            for (int q = 0; q < 2; ++q) {
                ulonglong2 b2 = *(const ulonglong2*)&Bs[buf][0][q * 32 + tx * 4];
                bpr[0][q * 2] = b2.x; bpr[0][q * 2 + 1] = b2.y;
            }
#pragma unroll
            for (int kk = 0; kk < BK; ++kk) {
                const int cs = kk & 1;
                if (kk + 1 < BK) {
#pragma unroll
                    for (int q = 0; q < 4; ++q) {
                        ulonglong2 a2 = *(const ulonglong2*)&As[buf][kk + 1][q * 32 + ty * 2];
                        apr[cs ^ 1][q * 2] = a2.x; apr[cs ^ 1][q * 2 + 1] = a2.y;
                    }
#pragma unroll
                    for (int q = 0; q < 2; ++q) {
                        ulonglong2 b2 = *(const ulonglong2*)&Bs[buf][kk + 1][q * 32 + tx * 4];
                        bpr[cs ^ 1][q * 2] = b2.x; bpr[cs ^ 1][q * 2 + 1] = b2.y;
                    }
                }
#pragma unroll
                for (int m = 0; m < 8; ++m)
#pragma unroll
                    for (int j = 0; j < 4; ++j)
                        ffma2(acc[m][j], apr[cs][m], bpr[cs][j]);
            }
        } else {
#pragma unroll
            for (int kk = 0; kk < BK; ++kk) {
                u64 ap[8];
#pragma unroll
                for (int q = 0; q < 4; ++q) {
                    ulonglong2 a2 = *(const ulonglong2*)&As[buf][kk][q * 32 + ty * 2];
                    ap[q * 2] = a2.x; ap[q * 2 + 1] = a2.y;
                }
                u64 bp[4];
#pragma unroll
                for (int q = 0; q < 2; ++q) {
                    ulonglong2 b2 = *(const ulonglong2*)&Bs[buf][kk][q * 32 + tx * 4];
                    bp[q * 2] = b2.x; bp[q * 2 + 1] = b2.y;
                }
#pragma unroll
                for (int m = 0; m < 8; ++m)
#pragma unroll
                    for (int j = 0; j < 4; ++j)
                        ffma2(acc[m][j], ap[m], bp[j]);
            }
        }
        if (t + 1 < nk) {
            int nb = buf ^ 1;
#pragma unroll
            for (int c = 0; c < 16; ++c)
                As[nb][c][tid] = dup32(((const float*)&pa[0])[c]);
#pragma unroll
            for (int q = 0; q < 2; ++q)
                *(float4*)&Bs[nb][brow][bcol + q * 4] = pb[q];
        }
        __syncthreads();
        buf ^= 1;
    }

    // ---- epilogue: bias + sigmoid + Bernoulli + optional per-row score partial ----
    float biasv[8];
#pragma unroll
    for (int q = 0; q < 2; ++q)
        *(float4*)&biasv[q * 4] = *(const float4*)(bias + n0 + q * 32 + tx * 4);
#pragma unroll
    for (int m = 0; m < 8; ++m) {
        int gm = m0 + ty * 8 + m;
        float sp = 0.f;
#pragma unroll
        for (int q = 0; q < 2; ++q) {
            int gn = n0 + q * 32 + tx * 4;
            float4 u4 = *(const float4*)(U + (size_t)gm * N + gn);
            float2 e0 = *(float2*)&acc[m][q * 2];
            float2 e1 = *(float2*)&acc[m][q * 2 + 1];
            float l[4] = { e0.x + biasv[q*4],   e0.y + biasv[q*4+1],
                           e1.x + biasv[q*4+2], e1.y + biasv[q*4+3] };
            float s[4];
#pragma unroll
            for (int j = 0; j < 4; ++j) {
                float pr = 1.0f / (1.0f + expf(-l[j]));   // libdevice expf + IEEE div
                s[j] = (pr > ((const float*)&u4)[j]) ? 1.0f : 0.0f;
            }
            *(float4*)(Out + (size_t)gm * N + gn) = make_float4(s[0], s[1], s[2], s[3]);
            if (SCORE) sp += s[0]*l[0] + s[1]*l[1] + s[2]*l[2] + s[3]*l[3];
        }
        if (SCORE) {
            sp += __shfl_xor_sync(0xffffffffu, sp, 1);
            sp += __shfl_xor_sync(0xffffffffu, sp, 2);
            sp += __shfl_xor_sync(0xffffffffu, sp, 4);
            if (tx == 0) Score[(size_t)gm * gridDim.x + blockIdx.x] = sp;
        }
    }
}

// ---------------- finalize: out[b] = (v.b_v + pos) - (neg + h2.b_h) ----------------
__global__ void k_finalize(const float* __restrict__ visible, const float* __restrict__ b_v,
                           const float* __restrict__ b_h, float* __restrict__ out)
{
    int b = blockIdx.x, tid = threadIdx.x;
    float acc = 0.f;
    const float* vr = visible + (size_t)b * RBM_V;
    for (int i = tid; i < RBM_V; i += 256) acc += vr[i] * b_v[i];
    const float* hr = g_h + (size_t)b * RBM_H;            // g_h holds h2 here
    for (int i = tid; i < RBM_H; i += 256) acc -= hr[i] * b_h[i];
    if (tid < 16) acc += g_pos[b * 16 + tid];             // 16 n-tiles (BN=64, N=1024)
    if (tid < 64) acc -= g_neg[b * 64 + tid];             // 64 n-tiles (BN=64, N=4096)
    __shared__ float red[256];
    red[tid] = acc;
    __syncthreads();
    for (int o = 128; o; o >>= 1) { if (tid < o) red[tid] += red[tid + o]; __syncthreads(); }
    if (tid == 0) out[b] = red[0];
}

// ---------------- launch ----------------
extern "C" void kernel_launch(void* const* d_in, const int* in_sizes, int n_in,
                              void* d_out, int out_size)
{
    const float* visible = (const float*)d_in[0];
    const float* b_v     = (const float*)d_in[1];
    const float* b_h     = (const float*)d_in[2];
    const float* W       = (const float*)d_in[3];
    const float* u_h0    = (const float*)d_in[4];
    const float* u_v     = (const float*)d_in[5];
    const float* u_h     = (const float*)d_in[6];
    float* out = (float*)d_out;

    float *WT, *hb, *vb, *pos, *neg;
    cudaGetSymbolAddress((void**)&WT,  g_WT);
    cudaGetSymbolAddress((void**)&hb,  g_h);
    cudaGetSymbolAddress((void**)&vb,  g_v);
    cudaGetSymbolAddress((void**)&pos, g_pos);
    cudaGetSymbolAddress((void**)&neg, g_neg);

    k_transpose<<<dim3(RBM_H / 32, RBM_V / 32), dim3(32, 8)>>>(W, WT);

    dim3 blk(128);
    dim3 gH(RBM_H / 64, RBM_B / 128);   // (16, 16) = 256 CTAs  (PIPE=1)
    dim3 gV(RBM_V / 64, RBM_B / 128);   // (64, 16) = 1024 CTAs (PIPE=0)

    const size_t BV = (size_t)RBM_B * RBM_V;
    const size_t BH = (size_t)RBM_B * RBM_H;

    // positive phase: h0 | data, fused pos-score
    k_gemm_sample<1,1><<<gH, blk>>>(visible, W,  b_h, u_h0,        hb, pos,    RBM_V, RBM_H);
    // Gibbs chain: v,h,v,h,v
    k_gemm_sample<0,0><<<gV, blk>>>(hb,      WT, b_v, u_v + 0*BV,  vb, nullptr, RBM_H, RBM_V);
    k_gemm_sample<0,1><<<gH, blk>>>(vb,      W,  b_h, u_h + 0*BH,  hb, nullptr, RBM_V, RBM_H);
    k_gemm_sample<0,0><<<gV, blk>>>(hb,      WT, b_v, u_v + 1*BV,  vb, nullptr, RBM_H, RBM_V);
    k_gemm_sample<0,1><<<gH, blk>>>(vb,      W,  b_h, u_h + 1*BH,  hb, nullptr, RBM_V, RBM_H);
    // last v-step: fused neg-score
    k_gemm_sample<2,0><<<gV, blk>>>(hb,      WT, b_v, u_v + 2*BV,  vb, neg,     RBM_H, RBM_V);

    k_finalize<<<RBM_B, 256>>>(visible, b_v, b_h, out);
}